// round 1
// baseline (speedup 1.0000x reference)
#include <cuda_runtime.h>
#include <cuda_bf16.h>

// Problem shapes (fixed by the dataset)
#define S_LEN 2048
#define BATCH 16
#define DDIM  2048

// Scratch for stage-1 result: altered[b][d], 16*2048 floats = 128 KB.
__device__ float g_altered[BATCH * DDIM];

// ---------------------------------------------------------------------------
// Kernel 1: altered[b][o] = sum_d state[b][d] * W[o][d] + bias[o]
// Block = 256 threads = 8 warps; each warp owns one output row o.
// state chunk [16][128] staged in shared (8 KB) per K-iteration.
// W row reads are fully coalesced float4 within the warp.
// ---------------------------------------------------------------------------
__global__ void __launch_bounds__(256, 8)
stage1_gemv(const float* __restrict__ state,
            const float* __restrict__ W,
            const float* __restrict__ bias)
{
    __shared__ float st[BATCH][128];

    const int tid    = threadIdx.x;
    const int warpId = tid >> 5;
    const int lane   = tid & 31;
    const int o      = blockIdx.x * 8 + warpId;   // output row (0..2047)

    float acc[BATCH];
#pragma unroll
    for (int b = 0; b < BATCH; ++b) acc[b] = 0.f;

    const float* wrow = W + (long)o * DDIM;

    for (int k0 = 0; k0 < DDIM; k0 += 128) {
        __syncthreads();
        // Cooperatively load state[:, k0:k0+128] -> shared (512 float4s, 256 thr x 2)
#pragma unroll
        for (int j = 0; j < 2; ++j) {
            int f4  = tid + j * 256;          // 0..511
            int b   = f4 >> 5;                // /32
            int w4  = f4 & 31;                // float4 index within chunk
            const float4 v = *(const float4*)(state + (long)b * DDIM + k0 + w4 * 4);
            *(float4*)&st[b][w4 * 4] = v;
        }
        __syncthreads();

        const float4 w4v = *(const float4*)(wrow + k0 + lane * 4);
#pragma unroll
        for (int b = 0; b < BATCH; ++b) {
            const float4 s4 = *(const float4*)&st[b][lane * 4];
            acc[b] += w4v.x * s4.x + w4v.y * s4.y + w4v.z * s4.z + w4v.w * s4.w;
        }
    }

    // Warp reduce each of the 16 accumulators.
#pragma unroll
    for (int off = 16; off > 0; off >>= 1) {
#pragma unroll
        for (int b = 0; b < BATCH; ++b)
            acc[b] += __shfl_down_sync(0xFFFFFFFFu, acc[b], off);
    }

    if (lane == 0) {
        const float bo = bias[o];
#pragma unroll
        for (int b = 0; b < BATCH; ++b)
            g_altered[b * DDIM + o] = acc[b] + bo;
    }
}

// ---------------------------------------------------------------------------
// Kernel 2: weights[b][s] = sum_d altered[b][d] * enc[s][b][d]
// Grid: (S/8, B). Block = 256 threads = 8 warps; warp w handles
// s = blockIdx.x*8 + w. altered[b][:] (8 KB) cached in shared.
// 16 unrolled independent float4 global loads per warp -> high MLP,
// fully coalesced 512B/warp/iter. Pure HBM streaming of the 256 MB tensor.
// ---------------------------------------------------------------------------
__global__ void __launch_bounds__(256, 8)
stage2_dots(const float* __restrict__ enc,
            float* __restrict__ out)
{
    __shared__ float alt[DDIM];

    const int tid    = threadIdx.x;
    const int warpId = tid >> 5;
    const int lane   = tid & 31;
    const int b      = blockIdx.y;
    const int s      = blockIdx.x * 8 + warpId;

    // Load altered[b][:] into shared: 2048 floats = 512 float4, 256 thr x 2.
#pragma unroll
    for (int j = 0; j < 2; ++j) {
        int f4 = tid + j * 256;
        *(float4*)&alt[f4 * 4] = *(const float4*)(g_altered + b * DDIM + f4 * 4);
    }
    __syncthreads();

    const float* row = enc + ((long)s * BATCH + b) * DDIM;

    float4 acc = make_float4(0.f, 0.f, 0.f, 0.f);
#pragma unroll
    for (int i = 0; i < 16; ++i) {
        const int d = i * 128 + lane * 4;
        const float4 e = *(const float4*)(row + d);
        const float4 a = *(const float4*)&alt[d];
        acc.x += e.x * a.x;
        acc.y += e.y * a.y;
        acc.z += e.z * a.z;
        acc.w += e.w * a.w;
    }

    float t = (acc.x + acc.y) + (acc.z + acc.w);
#pragma unroll
    for (int off = 16; off > 0; off >>= 1)
        t += __shfl_down_sync(0xFFFFFFFFu, t, off);

    if (lane == 0)
        out[b * S_LEN + s] = t;   // output shape [B, S]
}

extern "C" void kernel_launch(void* const* d_in, const int* in_sizes, int n_in,
                              void* d_out, int out_size)
{
    const float* enc   = (const float*)d_in[0];  // [S, B, D]
    const float* state = (const float*)d_in[1];  // [B, D]
    const float* W     = (const float*)d_in[2];  // [D, D]
    const float* bias  = (const float*)d_in[3];  // [D]
    float* out         = (float*)d_out;          // [B, S]

    stage1_gemv<<<DDIM / 8, 256>>>(state, W, bias);
    stage2_dots<<<dim3(S_LEN / 8, BATCH), 256>>>(enc, out);
}